// round 5
// baseline (speedup 1.0000x reference)
#include <cuda_runtime.h>

#define Lg 96
#define Hh 8
#define E 64
#define EH 128
#define R 64
#define RS 68
#define NT 256
#define SW(i, r) ((r) ^ ((((i) >> 2) & 15) << 2))

struct __align__(16) Smem {
    float yT[E][RS];
    float k1T[E][RS];
    float k2T[E][RS];
    float k3T[E][RS];
    float tmpT[E][RS];
    float S0T[E][RS];
    float HT[EH][RS];
    float W1[E][EH];
    float W2[EH][E];
    float b1[EH];
    float b2[E];
    float Ts[Lg];
};

__device__ __forceinline__ float tanh_fast(float x) {
    // 1 - 2/(e^{2x}+1): exact at both saturations (inf -> 1, 0 -> -1), rel err ~1e-6
    float e = __expf(2.0f * x);
    return 1.0f - __fdividef(2.0f, e + 1.0f);
}

__device__ __forceinline__ float4 ld4(const float* p) { return *(const float4*)p; }
__device__ __forceinline__ void st4(float* p, float4 v) { *(float4*)p = v; }
__device__ __forceinline__ float4 add4(float4 a, float4 b) {
    return make_float4(a.x + b.x, a.y + b.y, a.z + b.z, a.w + b.w);
}
__device__ __forceinline__ float4 sub4(float4 a, float4 b) {
    return make_float4(a.x - b.x, a.y - b.y, a.z - b.z, a.w - b.w);
}
__device__ __forceinline__ float4 scale4(float s, float4 a) {
    return make_float4(s * a.x, s * a.y, s * a.z, s * a.w);
}
__device__ __forceinline__ float4 fma4(float s, float4 a, float4 b) {  // s*a + b
    return make_float4(fmaf(s, a.x, b.x), fmaf(s, a.y, b.y),
                       fmaf(s, a.z, b.z), fmaf(s, a.w, b.w));
}

// One MLP eval: dst_k = f(src) = tanh(src@W1+b1)@W2+b2, with the RK4 stage
// combine fused into the GEMM2 writeback. mode: 0->k1, 1->k2, 2->k3, 3->k4+y update.
__device__ __forceinline__ void mlp_eval(Smem* s, const float (*__restrict__ src)[RS],
                                         int mode, float dt_f, float dt_b, int tid) {
    const int r0 = (tid & 15) * 4;   // batch-row tile origin (0..60)
    const int cg = tid >> 4;         // 0..15

    // ---- GEMM1: H = tanh(src @ W1 + b1), thread tile 4 rows x 8 cols ----
    {
        const int c0 = cg * 8;
        float acc[8][4];
#pragma unroll
        for (int i = 0; i < 8; i++)
#pragma unroll
            for (int j = 0; j < 4; j++) acc[i][j] = 0.0f;

#pragma unroll 8
        for (int k = 0; k < E; ++k) {
            float4 yv = ld4(&src[k][SW(k, r0)]);
            float4 wa = ld4(&s->W1[k][c0]);
            float4 wb = ld4(&s->W1[k][c0 + 4]);
            float ys[4] = {yv.x, yv.y, yv.z, yv.w};
            float ws[8] = {wa.x, wa.y, wa.z, wa.w, wb.x, wb.y, wb.z, wb.w};
#pragma unroll
            for (int ci = 0; ci < 8; ci++)
#pragma unroll
                for (int ri = 0; ri < 4; ri++)
                    acc[ci][ri] = fmaf(ws[ci], ys[ri], acc[ci][ri]);
        }
#pragma unroll
        for (int ci = 0; ci < 8; ci++) {
            int c = c0 + ci;
            float bb = s->b1[c];
            float4 h;
            h.x = tanh_fast(acc[ci][0] + bb);
            h.y = tanh_fast(acc[ci][1] + bb);
            h.z = tanh_fast(acc[ci][2] + bb);
            h.w = tanh_fast(acc[ci][3] + bb);
            st4(&s->HT[c][SW(c, r0)], h);
        }
    }
    __syncthreads();

    // ---- GEMM2: K = H @ W2 + b2, thread tile 4 rows x 4 cols, fused RK4 stage ----
    {
        const int c0 = cg * 4;
        float acc[4][4];
#pragma unroll
        for (int i = 0; i < 4; i++)
#pragma unroll
            for (int j = 0; j < 4; j++) acc[i][j] = 0.0f;

#pragma unroll 8
        for (int k = 0; k < EH; ++k) {
            float4 hv = ld4(&s->HT[k][SW(k, r0)]);
            float4 wv = ld4(&s->W2[k][c0]);
            float hs[4] = {hv.x, hv.y, hv.z, hv.w};
            float ws[4] = {wv.x, wv.y, wv.z, wv.w};
#pragma unroll
            for (int ci = 0; ci < 4; ci++)
#pragma unroll
                for (int ri = 0; ri < 4; ri++)
                    acc[ci][ri] = fmaf(ws[ci], hs[ri], acc[ci][ri]);
        }

        const float dt = (r0 < 32) ? dt_f : dt_b;
#pragma unroll
        for (int ci = 0; ci < 4; ci++) {
            int c = c0 + ci;
            int sr = SW(c, r0);
            float bb = s->b2[c];
            float4 kv = make_float4(acc[ci][0] + bb, acc[ci][1] + bb,
                                    acc[ci][2] + bb, acc[ci][3] + bb);
            float4 yv = ld4(&s->yT[c][sr]);
            if (mode == 0) {
                st4(&s->k1T[c][sr], kv);
                st4(&s->tmpT[c][sr], fma4(dt * (1.0f / 3.0f), kv, yv));  // y2 = y + dt*k1/3
            } else if (mode == 1) {
                float4 k1 = ld4(&s->k1T[c][sr]);
                st4(&s->k2T[c][sr], kv);
                // y3 = y + dt*(k2 - k1/3)
                st4(&s->tmpT[c][sr], fma4(dt, sub4(kv, scale4(1.0f / 3.0f, k1)), yv));
            } else if (mode == 2) {
                float4 k1 = ld4(&s->k1T[c][sr]);
                float4 k2 = ld4(&s->k2T[c][sr]);
                st4(&s->k3T[c][sr], kv);
                // y4 = y + dt*(k1 - k2 + k3)
                st4(&s->tmpT[c][sr], fma4(dt, add4(sub4(k1, k2), kv), yv));
            } else {
                float4 k1 = ld4(&s->k1T[c][sr]);
                float4 k2 = ld4(&s->k2T[c][sr]);
                float4 k3 = ld4(&s->k3T[c][sr]);
                // y += dt*(k1 + 3*(k2+k3) + k4)/8
                float4 sum = add4(add4(k1, kv), scale4(3.0f, add4(k2, k3)));
                st4(&s->yT[c][sr], fma4(dt * 0.125f, sum, yv));
            }
        }
    }
    __syncthreads();
}

__global__ void __launch_bounds__(NT, 1)
ode_kernel(const float* __restrict__ x, const float* __restrict__ Tg,
           const float* __restrict__ W1g, const float* __restrict__ b1g,
           const float* __restrict__ W2g, const float* __restrict__ b2g,
           float2* __restrict__ out) {
    extern __shared__ char smraw[];
    Smem* s = (Smem*)smraw;
    const int tid = threadIdx.x;
    const int pi = blockIdx.x >> 1;   // pair index 0..95 (descending work => LPT)
    const int half = blockIdx.x & 1;  // which 32-row half of each trajectory
    const int trajF = pi;
    const int trajB = 95 - pi;

    // --- load weights / biases / timeslots ---
    for (int t = tid; t < E * EH; t += NT) ((float*)s->W1)[t] = W1g[t];
    for (int t = tid; t < EH * E; t += NT) ((float*)s->W2)[t] = W2g[t];
    if (tid < EH) s->b1[tid] = b1g[tid];
    if (tid < E) s->b2[tid] = b2g[tid];
    if (tid < Lg) s->Ts[tid] = Tg[tid];

    // --- load initial states: rows 0..31 = fwd traj, 32..63 = bwd traj ---
    for (int t = tid; t < R * E; t += NT) {
        int u = t >> 6, e = t & 63;
        int traj = (u < 32) ? trajF : trajB;
        int grow = half * 32 + (u & 31);
        int b = grow >> 3, h = grow & 7;
        float v = x[(((b * Lg + traj) * Hh + h) << 6) + e];
        s->yT[e][SW(e, u)] = v;
        s->S0T[e][SW(e, u)] = v;
    }
    __syncthreads();

    // --- diagonal emission j == trajF (fwd traj only; every traj covered once) ---
    for (int t = tid; t < 32 * E; t += NT) {
        int u = t >> 6, e = t & 63;
        float x0 = s->S0T[e][SW(e, u)];
        int grow = half * 32 + u;
        int b = grow >> 3, h = grow & 7;
        size_t o = ((((size_t)(b * Lg + trajF) * Lg + trajF) * Hh + h) << 6) + e;
        out[o] = make_float2(x0, x0);
    }

    const int len = 95 - pi;  // identical for both batched trajectories
    for (int n = 0; n < len; ++n) {
        float dt_f = s->Ts[pi + n + 1] - s->Ts[pi + n];
        float dt_b = s->Ts[94 - pi - n] - s->Ts[95 - pi - n];  // negative

#pragma unroll 1
        for (int m = 0; m < 4; ++m)
            mlp_eval(s, (m == 0) ? (const float(*)[RS])s->yT : (const float(*)[RS])s->tmpT,
                     m, dt_f, dt_b, tid);

        const int jf = pi + n + 1;
        const int jb = 94 - pi - n;
        for (int t = tid; t < 32 * E; t += NT) {
            int u = t >> 6, e = t & 63;
            int grow = half * 32 + u;
            int b = grow >> 3, h = grow & 7;
            {  // fwd trajectory, GEMM row u
                float v = s->yT[e][SW(e, u)];
                float x0 = s->S0T[e][SW(e, u)];
                size_t o = ((((size_t)(b * Lg + trajF) * Lg + jf) * Hh + h) << 6) + e;
                out[o] = make_float2(x0, v);
            }
            {  // bwd trajectory, GEMM row u+32
                int u2 = u + 32;
                float v = s->yT[e][SW(e, u2)];
                float x0 = s->S0T[e][SW(e, u2)];
                size_t o = ((((size_t)(b * Lg + trajB) * Lg + jb) * Hh + h) << 6) + e;
                out[o] = make_float2(x0, v);
            }
        }
        // no extra sync needed: next eval's first internal barrier orders HT writes
        // after all emission reads of yT/S0T.
    }
}

extern "C" void kernel_launch(void* const* d_in, const int* in_sizes, int n_in,
                              void* d_out, int out_size) {
    (void)in_sizes; (void)n_in; (void)out_size;
    cudaFuncSetAttribute(ode_kernel, cudaFuncAttributeMaxDynamicSharedMemorySize,
                         (int)sizeof(Smem));
    ode_kernel<<<192, NT, sizeof(Smem)>>>(
        (const float*)d_in[0], (const float*)d_in[1], (const float*)d_in[2],
        (const float*)d_in[3], (const float*)d_in[4], (const float*)d_in[5],
        (float2*)d_out);
}

// round 6
// speedup vs baseline: 1.0788x; 1.0788x over previous
#include <cuda_runtime.h>

// ODELinear: 96 independent RK4(3/8) trajectories over a 64-wide MLP field.
// Unit = (idx-pair, row-half): 192 persistent CTAs, LPT-ordered by construction.
// This revision: f32x2 packed FMAs, RK4 stage state in registers (P/Q combos),
// emission fused into the final-stage writeback. Issue-bound -> fewer instructions.

#define Lg 96
#define Hh 8
#define E 64
#define EH 128
#define RS 68
#define NT 256
#define SW(i, r) ((r) ^ ((((i) >> 2) & 15) << 2))

typedef unsigned long long ull;

struct __align__(16) Smem {
    float yT[E][RS];     // state, transposed [feature][row], XOR-swizzled
    float tmpT[E][RS];   // RK4 stage input
    float HT[EH][RS];    // hidden activations, transposed
    float W1[E][EH];
    float W2[EH][E];
    float b1[EH];
    float b2[E];
    float Ts[Lg];
};

__device__ __forceinline__ float tanh_fast(float x) {
    // 1 - 2/(e^{2x}+1): exact at saturation, rel err ~1e-6
    float e = __expf(2.0f * x);
    return 1.0f - __fdividef(2.0f, e + 1.0f);
}

__device__ __forceinline__ float4 ld4(const float* p) { return *(const float4*)p; }
__device__ __forceinline__ void st4(float* p, float4 v) { *(float4*)p = v; }

// packed f32x2 helpers (B300: FFMA2 only reachable via PTX fma.rn.f32x2)
__device__ __forceinline__ ull fma2(ull a, ull b, ull c) {
    ull d;
    asm("fma.rn.f32x2 %0, %1, %2, %3;" : "=l"(d) : "l"(a), "l"(b), "l"(c));
    return d;
}
__device__ __forceinline__ ull pack2(float x) {
    ull d;
    asm("mov.b64 %0, {%1, %1};" : "=l"(d) : "f"(x));
    return d;
}
__device__ __forceinline__ void unpack2(ull v, float& lo, float& hi) {
    asm("mov.b64 {%0, %1}, %2;" : "=f"(lo), "=f"(hi) : "l"(v));
}

__global__ void __launch_bounds__(NT, 1)
ode_kernel(const float* __restrict__ x, const float* __restrict__ Tg,
           const float* __restrict__ W1g, const float* __restrict__ b1g,
           const float* __restrict__ W2g, const float* __restrict__ b2g,
           float2* __restrict__ out) {
    extern __shared__ char smraw[];
    Smem* s = (Smem*)smraw;
    const int tid = threadIdx.x;
    const int pi = blockIdx.x >> 1;   // pair index 0..95, descending work => LPT
    const int half = blockIdx.x & 1;  // which 32-row half of each trajectory
    const int trajF = pi;
    const int trajB = 95 - pi;

    // --- load weights / biases / timeslots ---
    for (int t = tid; t < E * EH; t += NT) ((float*)s->W1)[t] = W1g[t];
    for (int t = tid; t < EH * E; t += NT) ((float*)s->W2)[t] = W2g[t];
    if (tid < EH) s->b1[tid] = b1g[tid];
    if (tid < E) s->b2[tid] = b2g[tid];
    if (tid < Lg) s->Ts[tid] = Tg[tid];

    // --- initial states: rows 0..31 = fwd traj, 32..63 = bwd traj ---
    for (int t = tid; t < 64 * E; t += NT) {
        int u = t >> 6, e = t & 63;
        int traj = (u < 32) ? trajF : trajB;
        int grow = half * 32 + (u & 31);
        int b = grow >> 3, h = grow & 7;
        s->yT[e][SW(e, u)] = x[(((b * Lg + traj) * Hh + h) << 6) + e];
    }
    __syncthreads();

    const int r0 = (tid & 15) * 4;  // row tile origin (0..60)
    const int cg = tid >> 4;        // 0..15
    const int c0 = cg * 8;          // GEMM1 column base
    const int c0b = cg * 4;         // GEMM2 column base

    // per-thread persistent tiles [col 0..3][row 0..3] for GEMM2 cols c0b.., rows r0..
    float ytile[4][4], x0t[4][4], Pt[4][4], Qt[4][4];
#pragma unroll
    for (int c = 0; c < 4; ++c) {
        float4 v = ld4(&s->yT[c0b + c][SW(c0b + c, r0)]);
        ytile[c][0] = x0t[c][0] = v.x;
        ytile[c][1] = x0t[c][1] = v.y;
        ytile[c][2] = x0t[c][2] = v.z;
        ytile[c][3] = x0t[c][3] = v.w;
    }

    // emission row pointers (fixed per thread; only j varies per step)
    const int myTraj = (r0 < 32) ? trajF : trajB;
    float2* rp[4];
#pragma unroll
    for (int ri = 0; ri < 4; ++ri) {
        int grow = half * 32 + ((r0 + ri) & 31);
        int b = grow >> 3, h = grow & 7;
        rp[ri] = out + (size_t)(b * Lg + myTraj) * (Lg * Hh * 64) + h * 64 + c0b;
    }

    // diagonal emission j == trajF (fwd rows only; every traj covered once)
    if (r0 < 32) {
#pragma unroll
        for (int ri = 0; ri < 4; ++ri) {
            float4* p = (float4*)(rp[ri] + (size_t)trajF * (Hh * 64));
            p[0] = make_float4(x0t[0][ri], x0t[0][ri], x0t[1][ri], x0t[1][ri]);
            p[1] = make_float4(x0t[2][ri], x0t[2][ri], x0t[3][ri], x0t[3][ri]);
        }
    }

    int jcur = (r0 < 32) ? (pi + 1) : (94 - pi);
    const int jd = (r0 < 32) ? 1 : -1;

    const int len = 95 - pi;  // identical for both batched trajectories
    for (int n = 0; n < len; ++n) {
        const float dt_f = s->Ts[pi + n + 1] - s->Ts[pi + n];
        const float dt_b = s->Ts[94 - pi - n] - s->Ts[95 - pi - n];  // negative
        const float dt = (r0 < 32) ? dt_f : dt_b;

#pragma unroll 1
        for (int m = 0; m < 4; ++m) {
            const float(*src)[RS] = (m == 0) ? (const float(*)[RS])s->yT
                                             : (const float(*)[RS])s->tmpT;

            // ---- GEMM1: H = tanh(src @ W1 + b1); tile 4 rows x 8 cols (4 col-pairs) ----
            ull acc[4][4];
#pragma unroll
            for (int a = 0; a < 4; a++)
#pragma unroll
                for (int b = 0; b < 4; b++) acc[a][b] = 0ull;

#pragma unroll 8
            for (int k = 0; k < E; ++k) {
                float4 yv = ld4(&src[k][SW(k, r0)]);
                ulonglong2 wA = *(const ulonglong2*)&s->W1[k][c0];
                ulonglong2 wB = *(const ulonglong2*)&s->W1[k][c0 + 4];
                ull y0 = pack2(yv.x), y1 = pack2(yv.y), y2 = pack2(yv.z), y3 = pack2(yv.w);
                acc[0][0] = fma2(wA.x, y0, acc[0][0]);
                acc[0][1] = fma2(wA.x, y1, acc[0][1]);
                acc[0][2] = fma2(wA.x, y2, acc[0][2]);
                acc[0][3] = fma2(wA.x, y3, acc[0][3]);
                acc[1][0] = fma2(wA.y, y0, acc[1][0]);
                acc[1][1] = fma2(wA.y, y1, acc[1][1]);
                acc[1][2] = fma2(wA.y, y2, acc[1][2]);
                acc[1][3] = fma2(wA.y, y3, acc[1][3]);
                acc[2][0] = fma2(wB.x, y0, acc[2][0]);
                acc[2][1] = fma2(wB.x, y1, acc[2][1]);
                acc[2][2] = fma2(wB.x, y2, acc[2][2]);
                acc[2][3] = fma2(wB.x, y3, acc[2][3]);
                acc[3][0] = fma2(wB.y, y0, acc[3][0]);
                acc[3][1] = fma2(wB.y, y1, acc[3][1]);
                acc[3][2] = fma2(wB.y, y2, acc[3][2]);
                acc[3][3] = fma2(wB.y, y3, acc[3][3]);
            }
            {
                float hc[8][4];
#pragma unroll
                for (int cp = 0; cp < 4; cp++)
#pragma unroll
                    for (int r = 0; r < 4; r++) {
                        float lo, hi;
                        unpack2(acc[cp][r], lo, hi);
                        hc[2 * cp][r] = lo;
                        hc[2 * cp + 1][r] = hi;
                    }
#pragma unroll
                for (int ci = 0; ci < 8; ci++) {
                    int c = c0 + ci;
                    float bb = s->b1[c];
                    st4(&s->HT[c][SW(c, r0)],
                        make_float4(tanh_fast(hc[ci][0] + bb), tanh_fast(hc[ci][1] + bb),
                                    tanh_fast(hc[ci][2] + bb), tanh_fast(hc[ci][3] + bb)));
                }
            }
            __syncthreads();

            // ---- GEMM2: K = H @ W2 + b2; tile 4 rows x 4 cols (2 col-pairs) ----
            ull a2[2][4];
#pragma unroll
            for (int a = 0; a < 2; a++)
#pragma unroll
                for (int b = 0; b < 4; b++) a2[a][b] = 0ull;

#pragma unroll 8
            for (int k = 0; k < EH; ++k) {
                float4 hv = ld4(&s->HT[k][SW(k, r0)]);
                ulonglong2 wv = *(const ulonglong2*)&s->W2[k][c0b];
                ull h0 = pack2(hv.x), h1 = pack2(hv.y), h2 = pack2(hv.z), h3 = pack2(hv.w);
                a2[0][0] = fma2(wv.x, h0, a2[0][0]);
                a2[0][1] = fma2(wv.x, h1, a2[0][1]);
                a2[0][2] = fma2(wv.x, h2, a2[0][2]);
                a2[0][3] = fma2(wv.x, h3, a2[0][3]);
                a2[1][0] = fma2(wv.y, h0, a2[1][0]);
                a2[1][1] = fma2(wv.y, h1, a2[1][1]);
                a2[1][2] = fma2(wv.y, h2, a2[1][2]);
                a2[1][3] = fma2(wv.y, h3, a2[1][3]);
            }
            float kv[4][4];
#pragma unroll
            for (int cp = 0; cp < 2; cp++)
#pragma unroll
                for (int r = 0; r < 4; r++) {
                    float lo, hi;
                    unpack2(a2[cp][r], lo, hi);
                    kv[2 * cp][r] = lo;
                    kv[2 * cp + 1][r] = hi;
                }
#pragma unroll
            for (int c = 0; c < 4; c++) {
                float bb = s->b2[c0b + c];
#pragma unroll
                for (int r = 0; r < 4; r++) kv[c][r] += bb;
            }

            // ---- fused RK4 stage combine (P = k1-k2, Q = k1+3k2+3k3 running combos) ----
            if (m == 0) {
#pragma unroll
                for (int c = 0; c < 4; c++) {
                    float t4[4];
#pragma unroll
                    for (int r = 0; r < 4; r++) {
                        Pt[c][r] = kv[c][r];
                        Qt[c][r] = kv[c][r];
                        t4[r] = fmaf(dt * (1.0f / 3.0f), kv[c][r], ytile[c][r]);
                    }
                    st4(&s->tmpT[c0b + c][SW(c0b + c, r0)],
                        make_float4(t4[0], t4[1], t4[2], t4[3]));
                }
            } else if (m == 1) {
#pragma unroll
                for (int c = 0; c < 4; c++) {
                    float t4[4];
#pragma unroll
                    for (int r = 0; r < 4; r++) {
                        // y3 = y + dt*k2 - (dt/3)*k1
                        t4[r] = fmaf(dt, kv[c][r],
                                     fmaf(-dt * (1.0f / 3.0f), Pt[c][r], ytile[c][r]));
                        Qt[c][r] = fmaf(3.0f, kv[c][r], Qt[c][r]);  // k1 + 3k2
                        Pt[c][r] = Pt[c][r] - kv[c][r];             // k1 - k2
                    }
                    st4(&s->tmpT[c0b + c][SW(c0b + c, r0)],
                        make_float4(t4[0], t4[1], t4[2], t4[3]));
                }
            } else if (m == 2) {
#pragma unroll
                for (int c = 0; c < 4; c++) {
                    float t4[4];
#pragma unroll
                    for (int r = 0; r < 4; r++) {
                        // y4 = y + dt*(k1 - k2 + k3)
                        t4[r] = fmaf(dt, Pt[c][r] + kv[c][r], ytile[c][r]);
                        Qt[c][r] = fmaf(3.0f, kv[c][r], Qt[c][r]);  // k1 + 3k2 + 3k3
                    }
                    st4(&s->tmpT[c0b + c][SW(c0b + c, r0)],
                        make_float4(t4[0], t4[1], t4[2], t4[3]));
                }
            } else {
#pragma unroll
                for (int c = 0; c < 4; c++) {
#pragma unroll
                    for (int r = 0; r < 4; r++)
                        ytile[c][r] = fmaf(dt * 0.125f, Qt[c][r] + kv[c][r], ytile[c][r]);
                    st4(&s->yT[c0b + c][SW(c0b + c, r0)],
                        make_float4(ytile[c][0], ytile[c][1], ytile[c][2], ytile[c][3]));
                }
                // fused emission from registers
#pragma unroll
                for (int ri = 0; ri < 4; ++ri) {
                    float4* p = (float4*)(rp[ri] + (size_t)jcur * (Hh * 64));
                    p[0] = make_float4(x0t[0][ri], ytile[0][ri], x0t[1][ri], ytile[1][ri]);
                    p[1] = make_float4(x0t[2][ri], ytile[2][ri], x0t[3][ri], ytile[3][ri]);
                }
            }
            __syncthreads();
        }
        jcur += jd;
    }
}

extern "C" void kernel_launch(void* const* d_in, const int* in_sizes, int n_in,
                              void* d_out, int out_size) {
    (void)in_sizes; (void)n_in; (void)out_size;
    cudaFuncSetAttribute(ode_kernel, cudaFuncAttributeMaxDynamicSharedMemorySize,
                         (int)sizeof(Smem));
    ode_kernel<<<192, NT, sizeof(Smem)>>>(
        (const float*)d_in[0], (const float*)d_in[1], (const float*)d_in[2],
        (const float*)d_in[3], (const float*)d_in[4], (const float*)d_in[5],
        (float2*)d_out);
}